// round 11
// baseline (speedup 1.0000x reference)
#include <cuda_runtime.h>
#include <cuda_fp16.h>
#include <cstdint>

typedef unsigned int uint;

#define N_NODES 50000
#define N_EDGES 800000
#define N_RELS  65
#define D       64
#define N_GRAPHS 512

#define TILE_M 128
#define MAX_TILES (N_EDGES / TILE_M + N_RELS)   // 6315
#define P_BLOCKS 296
#define RGCN_SMEM 82944  // X 2x16K | W 2x8K | out 32K | dst 1K

// ---------------- scratch (device globals; no allocation) ----------------
__device__ float d_h0 [N_NODES * D];
__device__ float d_agg[N_NODES * D];
__device__ float d_g [N_GRAPHS * D];
__device__ float d_g2[N_GRAPHS * D];

__device__ uint d_hf_u[N_NODES * 32];           // fp16 X plane, 2 per uint
__device__ uint d_w1_u[3 * N_RELS * 2048];      // W^T fp16 main plane
__device__ uint d_w2_u[3 * N_RELS * 2048];      // W^T fp16 residual plane

__device__ int d_counts[N_RELS];                // zero-init; self-resetting
__device__ int d_cursor[N_RELS];
__device__ int d_psrc[N_EDGES];
__device__ int d_pdst[N_EDGES];
__device__ int d_tile_rel [MAX_TILES];
__device__ int d_tile_base[MAX_TILES];
__device__ int d_tile_cnt [MAX_TILES];
__device__ int d_num_tiles;

// ---------------- helpers ----------------
__device__ __forceinline__ void red_add_v4(float* p, float a, float b, float c, float d) {
    asm volatile("red.global.add.v4.f32 [%0], {%1, %2, %3, %4};"
                 :: "l"(p), "f"(a), "f"(b), "f"(c), "f"(d) : "memory");
}

__device__ __forceinline__ void mma_f16(float acc[4], const uint a[4], uint b0, uint b1) {
    asm volatile("mma.sync.aligned.m16n8k16.row.col.f32.f16.f16.f32 "
                 "{%0,%1,%2,%3}, {%4,%5,%6,%7}, {%8,%9}, {%0,%1,%2,%3};"
                 : "+f"(acc[0]), "+f"(acc[1]), "+f"(acc[2]), "+f"(acc[3])
                 : "r"(a[0]), "r"(a[1]), "r"(a[2]), "r"(a[3]), "r"(b0), "r"(b1));
}

__device__ __forceinline__ void ldsm_x4(uint r[4], uint32_t addr) {
    asm volatile("ldmatrix.sync.aligned.m8n8.x4.shared.b16 {%0,%1,%2,%3}, [%4];"
                 : "=r"(r[0]), "=r"(r[1]), "=r"(r[2]), "=r"(r[3]) : "r"(addr));
}

__device__ __forceinline__ uint32_t smem_u32(const void* p) {
    uint32_t a;
    asm("{ .reg .u64 t; cvta.to.shared.u64 t, %1; cvt.u32.u64 %0, t; }" : "=r"(a) : "l"(p));
    return a;
}

__device__ __forceinline__ unsigned short h_bits(__half h) {
    return *reinterpret_cast<unsigned short*>(&h);
}
__device__ __forceinline__ uint pack_f16x2(float a, float b) {
    __half h0 = __float2half_rn(a);
    __half h1 = __float2half_rn(b);
    return (uint)h_bits(h0) | ((uint)h_bits(h1) << 16);
}
// W split: w = w1 + w2 (both fp16)
__device__ __forceinline__ void splitw(float v0, float v1, uint& p1, uint& p2) {
    __half a0 = __float2half_rn(v0);
    __half a1 = __float2half_rn(v1);
    float r0 = v0 - __half2float(a0);
    float r1 = v1 - __half2float(a1);
    __half b0 = __float2half_rn(r0);
    __half b1 = __float2half_rn(r1);
    p1 = (uint)h_bits(a0) | ((uint)h_bits(a1) << 16);
    p2 = (uint)h_bits(b0) | ((uint)h_bits(b1) << 16);
}

// ---------------- prep: conv_x + zero agg/g + conv_w + hist (fused) ---------
__global__ void prep_kernel(const float* __restrict__ nf,
                            const int* __restrict__ et,
                            const float* __restrict__ W1,
                            const float* __restrict__ W2,
                            const float* __restrict__ W3) {
    int idx = blockIdx.x * 256 + threadIdx.x;

    if (idx < N_NODES * 32) {
        float2 v = ((const float2*)nf)[idx];
        d_hf_u[idx] = pack_f16x2(v.x, v.y);
        ((float2*)d_agg)[idx] = make_float2(0.f, 0.f);
    }
    if (idx < N_GRAPHS * 32) ((float2*)d_g)[idx] = make_float2(0.f, 0.f);

    if (idx < 3 * N_RELS * 64) {
        int l = idx / (N_RELS * 64), rc = idx % (N_RELS * 64);
        int r = rc >> 6, c = rc & 63;
        const float* W = (l == 0 ? W1 : (l == 1 ? W2 : W3)) + (size_t)r * 4096 + c;
        uint4* o1 = (uint4*)(d_w1_u + ((size_t)l * N_RELS + r) * 2048);
        uint4* o2 = (uint4*)(d_w2_u + ((size_t)l * N_RELS + r) * 2048);
#pragma unroll
        for (int q = 0; q < 8; q++) {
            uint u1[4], u2[4];
#pragma unroll
            for (int p = 0; p < 4; p++) {
                float v0 = W[(q * 8 + p * 2 + 0) * 64];
                float v1 = W[(q * 8 + p * 2 + 1) * 64];
                splitw(v0, v1, u1[p], u2[p]);
            }
            o1[c * 8 + q] = make_uint4(u1[0], u1[1], u1[2], u1[3]);
            o2[c * 8 + q] = make_uint4(u2[0], u2[1], u2[2], u2[3]);
        }
    }

    if (blockIdx.x < 256) {
        __shared__ int sc[N_RELS];
        for (int i = threadIdx.x; i < N_RELS; i += 256) sc[i] = 0;
        __syncthreads();
        for (int e = blockIdx.x * 256 + threadIdx.x; e < N_EDGES; e += 256 * 256)
            atomicAdd(&sc[et[e]], 1);
        __syncthreads();
        for (int i = threadIdx.x; i < N_RELS; i += 256)
            if (sc[i]) atomicAdd(&d_counts[i], sc[i]);
    }
}

// ---------------- scan + tile table (self-resets d_counts) ----------------
__global__ void scan_tiles_kernel() {
    __shared__ int offs[N_RELS];
    __shared__ int tstart[N_RELS];
    __shared__ int tcnt[N_RELS];
    if (threadIdx.x == 0) {
        int off = 0, ts = 0;
        for (int r = 0; r < N_RELS; r++) {
            int c = d_counts[r];
            offs[r] = off; tstart[r] = ts; tcnt[r] = c;
            d_cursor[r] = off;
            off += c;
            ts += (c + TILE_M - 1) / TILE_M;
        }
        d_num_tiles = ts;
    }
    __syncthreads();
    for (int r = threadIdx.x; r < N_RELS; r += blockDim.x) {
        d_counts[r] = 0;
        int c = tcnt[r], base = offs[r], t0 = tstart[r];
        int nt = (c + TILE_M - 1) / TILE_M;
        for (int t = 0; t < nt; t++) {
            d_tile_rel [t0 + t] = r;
            d_tile_base[t0 + t] = base + t * TILE_M;
            int rem = c - t * TILE_M;
            d_tile_cnt [t0 + t] = rem < TILE_M ? rem : TILE_M;
        }
    }
}

#define SC_EPT 8
__global__ void scatter_kernel(const int* __restrict__ et,
                               const int* __restrict__ src,
                               const int* __restrict__ dst) {
    __shared__ int lcnt[N_RELS];
    __shared__ int lbase[N_RELS];
    int start = blockIdx.x * blockDim.x * SC_EPT;
    for (int i = threadIdx.x; i < N_RELS; i += blockDim.x) lcnt[i] = 0;
    __syncthreads();
    int myrel[SC_EPT];
#pragma unroll
    for (int q = 0; q < SC_EPT; q++) {
        int e = start + threadIdx.x + q * blockDim.x;
        int r = (e < N_EDGES) ? et[e] : -1;
        myrel[q] = r;
        if (r >= 0) atomicAdd(&lcnt[r], 1);
    }
    __syncthreads();
    for (int i = threadIdx.x; i < N_RELS; i += blockDim.x) {
        int c = lcnt[i];
        lbase[i] = c ? atomicAdd(&d_cursor[i], c) : 0;
        lcnt[i] = 0;
    }
    __syncthreads();
#pragma unroll
    for (int q = 0; q < SC_EPT; q++) {
        int e = start + threadIdx.x + q * blockDim.x;
        int r = myrel[q];
        if (r >= 0) {
            int pos = lbase[r] + atomicAdd(&lcnt[r], 1);
            d_psrc[pos] = src[e];
            d_pdst[pos] = dst[e];
        }
    }
}

// ---------------- RGCN layer: fp16 2-term, 2 barriers/tile ------------------
// Warp grid: 4 edge-blocks(32 rows) x 4 col-quarters(16 cols).
// SMEM: X buf0 [0,16K) buf1 [16K,32K); W1 [32K,40K) W2 [40K,48K);
//       out [48K,80K); dst[2][128] at [80K,81K)
// Loop: wait; B1; prefetch(t+1); MMA; staging; B2; scatter; W(t+1) load.
__global__ void __launch_bounds__(512, 2) rgcn_mma_kernel(int layer)
{
    extern __shared__ __align__(16) uint smem[];
    int nt_total = d_num_tiles;
    int k = (nt_total + P_BLOCKS - 1) / P_BLOCKS;
    int t0 = (int)blockIdx.x * k;
    int t1 = t0 + k; if (t1 > nt_total) t1 = nt_total;
    if (t0 >= t1) return;

    int tid = threadIdx.x;
    uint sbase = smem_u32(smem);
    uint wb1 = sbase + 32768u;
    int* s_dstS = (int*)((char*)smem + 81920);   // [2][128]
    float* sOutF = (float*)((char*)smem + 49152);

    int lane = tid & 31, w = tid >> 5;
    int ebh = w & 3;          // edge block (32 rows)
    int cbq = w >> 2;         // col quarter (16 cols)
    int aSel = (lane >> 4) & 1;
    int aRowB = ebh * 32 + (lane & 15);
    int bRow = cbq * 16 + (lane & 7) + ((lane >> 4) & 1) * 8;
    int bSel = (lane >> 3) & 1;
    int g = lane >> 2, tq = lane & 3;

    // coalesced gather map: 8 threads per edge row (2 passes)
    int gm0 = tid >> 3, gc8 = tid & 7;
    // coalesced scatter map: 16 threads per edge row (4 passes)
    int sm0 = tid >> 4, sc16 = tid & 15;

    auto prefetch = [&](int t, int buf) {
        int base = d_tile_base[t];
        int cnt  = d_tile_cnt[t];
        uint xb = sbase + (uint)buf * 16384u;
        int* sd = s_dstS + buf * 128;
#pragma unroll
        for (int p = 0; p < 2; p++) {
            int m = gm0 + p * 64;
            int ei = base + m;
            int eic = ei < (N_EDGES - 1) ? ei : (N_EDGES - 1);
            int srow = d_psrc[eic];
            uint ssz = (m < cnt) ? 16u : 0u;
            const char* gsrc = (const char*)(d_hf_u + (size_t)srow * 32) + gc8 * 16;
            int ph = gc8 ^ (m & 7);
            uint dsts = xb + (uint)(m * 128 + ph * 16);
            asm volatile("cp.async.ca.shared.global [%0], [%1], 16, %2;"
                         :: "r"(dsts), "l"(gsrc), "r"(ssz) : "memory");
            if (gc8 == 0) sd[m] = (m < cnt) ? d_pdst[eic] : -1;
        }
        asm volatile("cp.async.commit_group;" ::: "memory");
    };

    auto load_w = [&](int rel) {
        const uint4* W1g = (const uint4*)(d_w1_u + ((size_t)layer * N_RELS + rel) * 2048);
        const uint4* W2g = (const uint4*)(d_w2_u + ((size_t)layer * N_RELS + rel) * 2048);
        uint4* w14 = (uint4*)((char*)smem + 32768);
        uint4* w24 = (uint4*)((char*)smem + 40960);
        int n = tid >> 3, c = tid & 7;
        int ph = c ^ (n & 7);
        w14[n * 8 + ph] = W1g[tid];
        w24[n * 8 + ph] = W2g[tid];
    };

    // pre-loop: X(t0) in flight, W(t0) staged; visibility via first B1
    prefetch(t0, 0);
    int cur_rel = d_tile_rel[t0];
    load_w(cur_rel);

    for (int t = t0; t < t1; t++) {
        int buf = (t - t0) & 1;

        asm volatile("cp.async.wait_group 0;" ::: "memory");
        __syncthreads();                          // B1: X/W/sd visible; sOut + bufs free

        bool has_next = (t + 1 < t1);
        if (has_next) prefetch(t + 1, buf ^ 1);   // covered by MMA+staging+scatter

        uint xbB = sbase + (uint)buf * 16384u;

        float acc[2][2][4];
#pragma unroll
        for (int a = 0; a < 2; a++)
#pragma unroll
            for (int b = 0; b < 2; b++) {
                acc[a][b][0] = acc[a][b][1] = acc[a][b][2] = acc[a][b][3] = 0.f;
            }

#pragma unroll
        for (int ks = 0; ks < 4; ks++) {
            int bChunk = (ks * 2 + bSel) ^ (bRow & 7);
            uint bAddr = wb1 + (uint)(bRow * 128 + bChunk * 16);
            uint bh[4], bl[4];
            ldsm_x4(bh, bAddr);
            ldsm_x4(bl, bAddr + 8192u);           // W2 plane
            int aRow0 = aRowB;
            int aChunk0 = (ks * 2 + aSel) ^ (aRow0 & 7);
            uint ah0[4];
            ldsm_x4(ah0, xbB + (uint)(aRow0 * 128 + aChunk0 * 16));
            int aRow1 = aRowB + 16;
            int aChunk1 = (ks * 2 + aSel) ^ (aRow1 & 7);
            uint ah1[4];
            ldsm_x4(ah1, xbB + (uint)(aRow1 * 128 + aChunk1 * 16));
            // round-robin across 4 independent accumulators (RAW distance 4)
            mma_f16(acc[0][0], ah0, bh[0], bh[1]);
            mma_f16(acc[0][1], ah0, bh[2], bh[3]);
            mma_f16(acc[1][0], ah1, bh[0], bh[1]);
            mma_f16(acc[1][1], ah1, bh[2], bh[3]);
            mma_f16(acc[0][0], ah0, bl[0], bl[1]);
            mma_f16(acc[0][1], ah0, bl[2], bl[3]);
            mma_f16(acc[1][0], ah1, bl[0], bl[1]);
            mma_f16(acc[1][1], ah1, bl[2], bl[3]);
        }

        // stage into out region (XOR layout, 64-float rows) — no barrier needed
        // before this: writes are warp-private slots, protected by B1 above.
#pragma unroll
        for (int mb = 0; mb < 2; mb++) {
#pragma unroll
            for (int n8 = 0; n8 < 2; n8++) {
                int R = ebh * 32 + mb * 16 + g;
                int C = cbq * 16 + n8 * 8 + 2 * tq;
                int pcA = C ^ ((R & 7) << 3);
                *(float2*)&sOutF[R * 64 + pcA] = make_float2(acc[mb][n8][0], acc[mb][n8][1]);
                int R2 = R + 8;
                int pcB = C ^ ((R2 & 7) << 3);
                *(float2*)&sOutF[R2 * 64 + pcB] = make_float2(acc[mb][n8][2], acc[mb][n8][3]);
            }
        }
        __syncthreads();                          // B2: staging visible

        // coalesced scatter: 16 threads per edge -> whole 256B row per half-warp
        {
            int* sd = s_dstS + buf * 128;
#pragma unroll
            for (int p = 0; p < 4; p++) {
                int m = sm0 + p * 32;
                int dn = sd[m];
                if (dn >= 0) {
                    int pc = (sc16 * 4) ^ ((m & 7) << 3);
                    float4 v = *(const float4*)&sOutF[m * 64 + pc];
                    red_add_v4(d_agg + (size_t)dn * 64 + sc16 * 4, v.x, v.y, v.z, v.w);
                }
            }
        }

        // stage next W in the post-B2 shadow (all warps past MMA(t))
        if (has_next) {
            int nrel = d_tile_rel[t + 1];
            if (nrel != cur_rel) {
                load_w(nrel);
                cur_rel = nrel;
            }
        }
    }
}

// ---------------- bias + relu + fp16 convert + agg re-zero ----------------
__global__ void bias_relu_kernel(const float* __restrict__ b, int last) {
    int idx = blockIdx.x * blockDim.x + threadIdx.x;
    if (idx >= N_NODES * 32) return;
    int c0 = (idx * 2) & 63;
    float2 a = ((const float2*)d_agg)[idx];
    ((float2*)d_agg)[idx] = make_float2(0.f, 0.f);
    float v0 = fmaxf(a.x + b[c0],     0.0f);
    float v1 = fmaxf(a.y + b[c0 + 1], 0.0f);
    if (last) ((float2*)d_h0)[idx] = make_float2(v0, v1);
    d_hf_u[idx] = pack_f16x2(v0, v1);
}

// ---------------- graph sum-pool (reads d_h0) ----------------
__global__ void pool_kernel(const int* __restrict__ gid) {
    int idx = blockIdx.x * blockDim.x + threadIdx.x;
    if (idx >= N_NODES * 16) return;
    int n = idx >> 4, c4 = idx & 15;
    float4 v = ((const float4*)(d_h0 + (size_t)n * 64))[c4];
    float* p = d_g + (size_t)gid[n] * 64 + c4 * 4;
    red_add_v4(p, v.x, v.y, v.z, v.w);
}

// ---------------- FC layers ----------------
__global__ void fc64_kernel(int insel, int outsel,
                            const float* __restrict__ W,
                            const float* __restrict__ b) {
    int idx = blockIdx.x * blockDim.x + threadIdx.x;
    if (idx >= N_GRAPHS * 64) return;
    int r = idx >> 6, c = idx & 63;
    const float* x = (insel == 0 ? d_g : d_g2) + r * 64;
    float acc = b[c];
#pragma unroll
    for (int d = 0; d < 64; d++) acc = fmaf(x[d], W[d * 64 + c], acc);
    float v = fmaxf(acc, 0.0f);
    if (outsel == 0) d_g[idx] = v; else d_g2[idx] = v;
}

__global__ void pred_kernel(const float* __restrict__ W,
                            const float* __restrict__ b,
                            float* __restrict__ out) {
    int idx = blockIdx.x * blockDim.x + threadIdx.x;
    if (idx >= N_GRAPHS * 2) return;
    int r = idx >> 1, c = idx & 1;
    const float* x = d_g2 + r * 64;
    float acc = b[c];
#pragma unroll
    for (int d = 0; d < 64; d++) acc = fmaf(x[d], W[d * 2 + c], acc);
    out[idx] = acc;
}

// ---------------- launch ----------------
extern "C" void kernel_launch(void* const* d_in, const int* in_sizes, int n_in,
                              void* d_out, int out_size) {
    const float* node_feats = (const float*)d_in[0];
    const int*   etypes     = (const int*)d_in[1];
    const int*   src        = (const int*)d_in[2];
    const int*   dst        = (const int*)d_in[3];
    const int*   gid        = (const int*)d_in[4];
    const float* Wr[3] = { (const float*)d_in[5], (const float*)d_in[7], (const float*)d_in[9] };
    const float* br[3] = { (const float*)d_in[6], (const float*)d_in[8], (const float*)d_in[10] };
    const float* fcW[3] = { (const float*)d_in[11], (const float*)d_in[13], (const float*)d_in[15] };
    const float* fcb[3] = { (const float*)d_in[12], (const float*)d_in[14], (const float*)d_in[16] };
    const float* predW = (const float*)d_in[17];
    const float* predb = (const float*)d_in[18];

    static int smem_set = 0;
    if (!smem_set) {
        cudaFuncSetAttribute(rgcn_mma_kernel,
                             cudaFuncAttributeMaxDynamicSharedMemorySize, RGCN_SMEM);
        smem_set = 1;
    }

    const int pgrid = (N_NODES * 32 + 255) / 256;

    prep_kernel<<<pgrid, 256>>>(node_feats, etypes, Wr[0], Wr[1], Wr[2]);
    scan_tiles_kernel<<<1, 128>>>();
    scatter_kernel<<<(N_EDGES + 256 * SC_EPT - 1) / (256 * SC_EPT), 256>>>(etypes, src, dst);

    for (int L = 0; L < 3; L++) {
        rgcn_mma_kernel<<<P_BLOCKS, 512, RGCN_SMEM>>>(L);
        bias_relu_kernel<<<pgrid, 256>>>(br[L], L == 2 ? 1 : 0);
    }

    pool_kernel<<<(N_NODES * 16 + 255) / 256, 256>>>(gid);

    const int fgrid = (N_GRAPHS * 64 + 255) / 256;
    fc64_kernel<<<fgrid, 256>>>(0, 1, fcW[0], fcb[0]);
    fc64_kernel<<<fgrid, 256>>>(1, 0, fcW[1], fcb[1]);
    fc64_kernel<<<fgrid, 256>>>(0, 1, fcW[2], fcb[2]);
    pred_kernel<<<(N_GRAPHS * 2 + 255) / 256, 256>>>(predW, predb, (float*)d_out);
}

// round 12
// speedup vs baseline: 1.4717x; 1.4717x over previous
#include <cuda_runtime.h>
#include <cuda_fp16.h>
#include <cstdint>

typedef unsigned int uint;

#define N_NODES 50000
#define N_EDGES 800000
#define N_RELS  65
#define D       64
#define N_GRAPHS 512

#define TILE_M 128
#define MAX_TILES (N_EDGES / TILE_M + N_RELS)   // 6315
#define P_BLOCKS 296
#define RGCN_SMEM 74752  // X 2x16K | W 8K | out 32K | dst 1K

// ---------------- scratch (device globals; no allocation) ----------------
__device__ float d_h0 [N_NODES * D];
__device__ float d_agg[N_NODES * D];
__device__ float d_g [N_GRAPHS * D];
__device__ float d_g2[N_GRAPHS * D];

__device__ uint d_hf_u[N_NODES * 32];           // fp16 X plane, 2 per uint
__device__ uint d_w1_u[3 * N_RELS * 2048];      // W^T fp16 plane

__device__ int d_counts[N_RELS];                // zero-init; self-resetting
__device__ int d_cursor[N_RELS];
__device__ int d_psrc[N_EDGES];
__device__ int d_pdst[N_EDGES];
__device__ int d_tile_rel [MAX_TILES];
__device__ int d_tile_base[MAX_TILES];
__device__ int d_tile_cnt [MAX_TILES];
__device__ int d_num_tiles;

// ---------------- helpers ----------------
__device__ __forceinline__ void red_add_v4(float* p, float a, float b, float c, float d) {
    asm volatile("red.global.add.v4.f32 [%0], {%1, %2, %3, %4};"
                 :: "l"(p), "f"(a), "f"(b), "f"(c), "f"(d) : "memory");
}

__device__ __forceinline__ void mma_f16(float acc[4], const uint a[4], uint b0, uint b1) {
    asm volatile("mma.sync.aligned.m16n8k16.row.col.f32.f16.f16.f32 "
                 "{%0,%1,%2,%3}, {%4,%5,%6,%7}, {%8,%9}, {%0,%1,%2,%3};"
                 : "+f"(acc[0]), "+f"(acc[1]), "+f"(acc[2]), "+f"(acc[3])
                 : "r"(a[0]), "r"(a[1]), "r"(a[2]), "r"(a[3]), "r"(b0), "r"(b1));
}

__device__ __forceinline__ void ldsm_x4(uint r[4], uint32_t addr) {
    asm volatile("ldmatrix.sync.aligned.m8n8.x4.shared.b16 {%0,%1,%2,%3}, [%4];"
                 : "=r"(r[0]), "=r"(r[1]), "=r"(r[2]), "=r"(r[3]) : "r"(addr));
}

__device__ __forceinline__ uint32_t smem_u32(const void* p) {
    uint32_t a;
    asm("{ .reg .u64 t; cvta.to.shared.u64 t, %1; cvt.u32.u64 %0, t; }" : "=r"(a) : "l"(p));
    return a;
}

__device__ __forceinline__ unsigned short h_bits(__half h) {
    return *reinterpret_cast<unsigned short*>(&h);
}
__device__ __forceinline__ uint pack_f16x2(float a, float b) {
    __half h0 = __float2half_rn(a);
    __half h1 = __float2half_rn(b);
    return (uint)h_bits(h0) | ((uint)h_bits(h1) << 16);
}

// ---------------- prep: conv_x + zero agg/g + conv_w + hist (fused) ---------
__global__ void prep_kernel(const float* __restrict__ nf,
                            const int* __restrict__ et,
                            const float* __restrict__ W1,
                            const float* __restrict__ W2,
                            const float* __restrict__ W3) {
    int idx = blockIdx.x * 256 + threadIdx.x;

    if (idx < N_NODES * 32) {
        float2 v = ((const float2*)nf)[idx];
        d_hf_u[idx] = pack_f16x2(v.x, v.y);
        ((float2*)d_agg)[idx] = make_float2(0.f, 0.f);
    }
    if (idx < N_GRAPHS * 32) ((float2*)d_g)[idx] = make_float2(0.f, 0.f);

    if (idx < 3 * N_RELS * 64) {
        int l = idx / (N_RELS * 64), rc = idx % (N_RELS * 64);
        int r = rc >> 6, c = rc & 63;
        const float* W = (l == 0 ? W1 : (l == 1 ? W2 : W3)) + (size_t)r * 4096 + c;
        uint4* o1 = (uint4*)(d_w1_u + ((size_t)l * N_RELS + r) * 2048);
#pragma unroll
        for (int q = 0; q < 8; q++) {
            uint u1[4];
#pragma unroll
            for (int p = 0; p < 4; p++) {
                float v0 = W[(q * 8 + p * 2 + 0) * 64];
                float v1 = W[(q * 8 + p * 2 + 1) * 64];
                u1[p] = pack_f16x2(v0, v1);
            }
            o1[c * 8 + q] = make_uint4(u1[0], u1[1], u1[2], u1[3]);
        }
    }

    if (blockIdx.x < 256) {
        __shared__ int sc[N_RELS];
        for (int i = threadIdx.x; i < N_RELS; i += 256) sc[i] = 0;
        __syncthreads();
        for (int e = blockIdx.x * 256 + threadIdx.x; e < N_EDGES; e += 256 * 256)
            atomicAdd(&sc[et[e]], 1);
        __syncthreads();
        for (int i = threadIdx.x; i < N_RELS; i += 256)
            if (sc[i]) atomicAdd(&d_counts[i], sc[i]);
    }
}

// ---------------- scan + tile table (self-resets d_counts) ----------------
__global__ void scan_tiles_kernel() {
    __shared__ int offs[N_RELS];
    __shared__ int tstart[N_RELS];
    __shared__ int tcnt[N_RELS];
    if (threadIdx.x == 0) {
        int off = 0, ts = 0;
        for (int r = 0; r < N_RELS; r++) {
            int c = d_counts[r];
            offs[r] = off; tstart[r] = ts; tcnt[r] = c;
            d_cursor[r] = off;
            off += c;
            ts += (c + TILE_M - 1) / TILE_M;
        }
        d_num_tiles = ts;
    }
    __syncthreads();
    for (int r = threadIdx.x; r < N_RELS; r += blockDim.x) {
        d_counts[r] = 0;
        int c = tcnt[r], base = offs[r], t0 = tstart[r];
        int nt = (c + TILE_M - 1) / TILE_M;
        for (int t = 0; t < nt; t++) {
            d_tile_rel [t0 + t] = r;
            d_tile_base[t0 + t] = base + t * TILE_M;
            int rem = c - t * TILE_M;
            d_tile_cnt [t0 + t] = rem < TILE_M ? rem : TILE_M;
        }
    }
}

#define SC_EPT 8
__global__ void scatter_kernel(const int* __restrict__ et,
                               const int* __restrict__ src,
                               const int* __restrict__ dst) {
    __shared__ int lcnt[N_RELS];
    __shared__ int lbase[N_RELS];
    int start = blockIdx.x * blockDim.x * SC_EPT;
    for (int i = threadIdx.x; i < N_RELS; i += blockDim.x) lcnt[i] = 0;
    __syncthreads();
    int myrel[SC_EPT];
#pragma unroll
    for (int q = 0; q < SC_EPT; q++) {
        int e = start + threadIdx.x + q * blockDim.x;
        int r = (e < N_EDGES) ? et[e] : -1;
        myrel[q] = r;
        if (r >= 0) atomicAdd(&lcnt[r], 1);
    }
    __syncthreads();
    for (int i = threadIdx.x; i < N_RELS; i += blockDim.x) {
        int c = lcnt[i];
        lbase[i] = c ? atomicAdd(&d_cursor[i], c) : 0;
        lcnt[i] = 0;
    }
    __syncthreads();
#pragma unroll
    for (int q = 0; q < SC_EPT; q++) {
        int e = start + threadIdx.x + q * blockDim.x;
        int r = myrel[q];
        if (r >= 0) {
            int pos = lbase[r] + atomicAdd(&lcnt[r], 1);
            d_psrc[pos] = src[e];
            d_pdst[pos] = dst[e];
        }
    }
}

// ---------------- RGCN layer: fp16 single-plane W, R10 loop structure -------
// Warp grid: 4 edge-blocks(32 rows) x 4 col-quarters(16 cols).
// SMEM: X buf0 [0,16K) buf1 [16K,32K); W1 [32K,40K);
//       out [40K,72K); dst[2][128] at [72K,73K)
__global__ void __launch_bounds__(512, 2) rgcn_mma_kernel(int layer)
{
    extern __shared__ __align__(16) uint smem[];
    int nt_total = d_num_tiles;
    int k = (nt_total + P_BLOCKS - 1) / P_BLOCKS;
    int t0 = (int)blockIdx.x * k;
    int t1 = t0 + k; if (t1 > nt_total) t1 = nt_total;
    if (t0 >= t1) return;

    int tid = threadIdx.x;
    uint sbase = smem_u32(smem);
    uint wb1 = sbase + 32768u;
    int* s_dstS = (int*)((char*)smem + 73728);   // [2][128]
    float* sOutF = (float*)((char*)smem + 40960);

    int lane = tid & 31, w = tid >> 5;
    int ebh = w & 3;          // edge block (32 rows)
    int cbq = w >> 2;         // col quarter (16 cols)
    int aSel = (lane >> 4) & 1;
    int aRowB = ebh * 32 + (lane & 15);
    int bRow = cbq * 16 + (lane & 7) + ((lane >> 4) & 1) * 8;
    int bSel = (lane >> 3) & 1;
    int g = lane >> 2, tq = lane & 3;

    // coalesced gather map: 8 threads per edge row (2 passes)
    int gm0 = tid >> 3, gc8 = tid & 7;
    // coalesced scatter map: 16 threads per edge row (4 passes)
    int sm0 = tid >> 4, sc16 = tid & 15;

    int cur_rel = -1;

    auto prefetch = [&](int t, int buf) {
        int base = d_tile_base[t];
        int cnt  = d_tile_cnt[t];
        uint xb = sbase + (uint)buf * 16384u;
        int* sd = s_dstS + buf * 128;
#pragma unroll
        for (int p = 0; p < 2; p++) {
            int m = gm0 + p * 64;
            int ei = base + m;
            int eic = ei < (N_EDGES - 1) ? ei : (N_EDGES - 1);
            int srow = d_psrc[eic];
            uint ssz = (m < cnt) ? 16u : 0u;
            const char* gsrc = (const char*)(d_hf_u + (size_t)srow * 32) + gc8 * 16;
            int ph = gc8 ^ (m & 7);
            uint dsts = xb + (uint)(m * 128 + ph * 16);
            asm volatile("cp.async.ca.shared.global [%0], [%1], 16, %2;"
                         :: "r"(dsts), "l"(gsrc), "r"(ssz) : "memory");
            if (gc8 == 0) sd[m] = (m < cnt) ? d_pdst[eic] : -1;
        }
        asm volatile("cp.async.commit_group;" ::: "memory");
    };

    prefetch(t0, 0);

    for (int t = t0; t < t1; t++) {
        int buf = (t - t0) & 1;

        if (t > t0) __syncthreads();              // scatter reads of t-1 done
        bool has_next = (t + 1 < t1);
        if (has_next) prefetch(t + 1, buf ^ 1);

        int rel = d_tile_rel[t];
        if (rel != cur_rel) {
            cur_rel = rel;
            const uint4* W1g = (const uint4*)(d_w1_u + ((size_t)layer * N_RELS + rel) * 2048);
            uint4* w14 = (uint4*)((char*)smem + 32768);
            int n = tid >> 3, c = tid & 7;
            int ph = c ^ (n & 7);
            w14[n * 8 + ph] = W1g[tid];
            // visibility covered by the post-wait_group __syncthreads below
        }

        if (has_next) asm volatile("cp.async.wait_group 1;" ::: "memory");
        else          asm volatile("cp.async.wait_group 0;" ::: "memory");
        __syncthreads();                          // X[t] + W + s_dst visible

        uint xbB = sbase + (uint)buf * 16384u;

        float acc[2][2][4];
#pragma unroll
        for (int a = 0; a < 2; a++)
#pragma unroll
            for (int b = 0; b < 2; b++) {
                acc[a][b][0] = acc[a][b][1] = acc[a][b][2] = acc[a][b][3] = 0.f;
            }

#pragma unroll
        for (int ks = 0; ks < 4; ks++) {
            int bChunk = (ks * 2 + bSel) ^ (bRow & 7);
            uint bAddr = wb1 + (uint)(bRow * 128 + bChunk * 16);
            uint bh[4];
            ldsm_x4(bh, bAddr);
#pragma unroll
            for (int mb = 0; mb < 2; mb++) {
                int aRow = aRowB + mb * 16;
                int aChunk = (ks * 2 + aSel) ^ (aRow & 7);
                uint aAddr = xbB + (uint)(aRow * 128 + aChunk * 16);
                uint ah[4];
                ldsm_x4(ah, aAddr);
                mma_f16(acc[mb][0], ah, bh[0], bh[1]);
                mma_f16(acc[mb][1], ah, bh[2], bh[3]);
            }
        }
        __syncthreads();                          // all ldsm of buf done

        // stage into dedicated out region (XOR layout, 64-float rows)
#pragma unroll
        for (int mb = 0; mb < 2; mb++) {
#pragma unroll
            for (int n8 = 0; n8 < 2; n8++) {
                int R = ebh * 32 + mb * 16 + g;
                int C = cbq * 16 + n8 * 8 + 2 * tq;
                int pcA = C ^ ((R & 7) << 3);
                *(float2*)&sOutF[R * 64 + pcA] = make_float2(acc[mb][n8][0], acc[mb][n8][1]);
                int R2 = R + 8;
                int pcB = C ^ ((R2 & 7) << 3);
                *(float2*)&sOutF[R2 * 64 + pcB] = make_float2(acc[mb][n8][2], acc[mb][n8][3]);
            }
        }
        __syncthreads();                          // staging visible

        // coalesced scatter: 16 threads per edge -> whole 256B row per half-warp
        {
            int* sd = s_dstS + buf * 128;
#pragma unroll
            for (int p = 0; p < 4; p++) {
                int m = sm0 + p * 32;
                int dn = sd[m];
                if (dn >= 0) {
                    int pc = (sc16 * 4) ^ ((m & 7) << 3);
                    float4 v = *(const float4*)&sOutF[m * 64 + pc];
                    red_add_v4(d_agg + (size_t)dn * 64 + sc16 * 4, v.x, v.y, v.z, v.w);
                }
            }
        }
    }
}

// ---------------- bias + relu + fp16 convert + agg re-zero ----------------
__global__ void bias_relu_kernel(const float* __restrict__ b, int last) {
    int idx = blockIdx.x * blockDim.x + threadIdx.x;
    if (idx >= N_NODES * 32) return;
    int c0 = (idx * 2) & 63;
    float2 a = ((const float2*)d_agg)[idx];
    ((float2*)d_agg)[idx] = make_float2(0.f, 0.f);
    float v0 = fmaxf(a.x + b[c0],     0.0f);
    float v1 = fmaxf(a.y + b[c0 + 1], 0.0f);
    if (last) ((float2*)d_h0)[idx] = make_float2(v0, v1);
    d_hf_u[idx] = pack_f16x2(v0, v1);
}

// ---------------- graph sum-pool (reads d_h0) ----------------
__global__ void pool_kernel(const int* __restrict__ gid) {
    int idx = blockIdx.x * blockDim.x + threadIdx.x;
    if (idx >= N_NODES * 16) return;
    int n = idx >> 4, c4 = idx & 15;
    float4 v = ((const float4*)(d_h0 + (size_t)n * 64))[c4];
    float* p = d_g + (size_t)gid[n] * 64 + c4 * 4;
    red_add_v4(p, v.x, v.y, v.z, v.w);
}

// ---------------- FC layers ----------------
__global__ void fc64_kernel(int insel, int outsel,
                            const float* __restrict__ W,
                            const float* __restrict__ b) {
    int idx = blockIdx.x * blockDim.x + threadIdx.x;
    if (idx >= N_GRAPHS * 64) return;
    int r = idx >> 6, c = idx & 63;
    const float* x = (insel == 0 ? d_g : d_g2) + r * 64;
    float acc = b[c];
#pragma unroll
    for (int d = 0; d < 64; d++) acc = fmaf(x[d], W[d * 64 + c], acc);
    float v = fmaxf(acc, 0.0f);
    if (outsel == 0) d_g[idx] = v; else d_g2[idx] = v;
}

__global__ void pred_kernel(const float* __restrict__ W,
                            const float* __restrict__ b,
                            float* __restrict__ out) {
    int idx = blockIdx.x * blockDim.x + threadIdx.x;
    if (idx >= N_GRAPHS * 2) return;
    int r = idx >> 1, c = idx & 1;
    const float* x = d_g2 + r * 64;
    float acc = b[c];
#pragma unroll
    for (int d = 0; d < 64; d++) acc = fmaf(x[d], W[d * 2 + c], acc);
    out[idx] = acc;
}

// ---------------- launch ----------------
extern "C" void kernel_launch(void* const* d_in, const int* in_sizes, int n_in,
                              void* d_out, int out_size) {
    const float* node_feats = (const float*)d_in[0];
    const int*   etypes     = (const int*)d_in[1];
    const int*   src        = (const int*)d_in[2];
    const int*   dst        = (const int*)d_in[3];
    const int*   gid        = (const int*)d_in[4];
    const float* Wr[3] = { (const float*)d_in[5], (const float*)d_in[7], (const float*)d_in[9] };
    const float* br[3] = { (const float*)d_in[6], (const float*)d_in[8], (const float*)d_in[10] };
    const float* fcW[3] = { (const float*)d_in[11], (const float*)d_in[13], (const float*)d_in[15] };
    const float* fcb[3] = { (const float*)d_in[12], (const float*)d_in[14], (const float*)d_in[16] };
    const float* predW = (const float*)d_in[17];
    const float* predb = (const float*)d_in[18];

    static int smem_set = 0;
    if (!smem_set) {
        cudaFuncSetAttribute(rgcn_mma_kernel,
                             cudaFuncAttributeMaxDynamicSharedMemorySize, RGCN_SMEM);
        smem_set = 1;
    }

    const int pgrid = (N_NODES * 32 + 255) / 256;

    prep_kernel<<<pgrid, 256>>>(node_feats, etypes, Wr[0], Wr[1], Wr[2]);
    scan_tiles_kernel<<<1, 128>>>();
    scatter_kernel<<<(N_EDGES + 256 * SC_EPT - 1) / (256 * SC_EPT), 256>>>(etypes, src, dst);

    for (int L = 0; L < 3; L++) {
        rgcn_mma_kernel<<<P_BLOCKS, 512, RGCN_SMEM>>>(L);
        bias_relu_kernel<<<pgrid, 256>>>(br[L], L == 2 ? 1 : 0);
    }

    pool_kernel<<<(N_NODES * 16 + 255) / 256, 256>>>(gid);

    const int fgrid = (N_GRAPHS * 64 + 255) / 256;
    fc64_kernel<<<fgrid, 256>>>(0, 1, fcW[0], fcb[0]);
    fc64_kernel<<<fgrid, 256>>>(1, 0, fcW[1], fcb[1]);
    fc64_kernel<<<fgrid, 256>>>(0, 1, fcW[2], fcb[2]);
    pred_kernel<<<(N_GRAPHS * 2 + 255) / 256, 256>>>(predW, predb, (float*)d_out);
}

// round 13
// speedup vs baseline: 1.4875x; 1.0107x over previous
#include <cuda_runtime.h>
#include <cuda_fp16.h>
#include <cstdint>

typedef unsigned int uint;

#define N_NODES 50000
#define N_EDGES 800000
#define N_RELS  65
#define D       64
#define N_GRAPHS 512

#define TILE_M 128
#define MAX_TILES (N_EDGES / TILE_M + N_RELS)   // 6315
#define P_BLOCKS 296
#define RGCN_SMEM 75264  // X 2x16K | W 8K | out 32K | sd 3x512B

// ---------------- scratch (device globals; no allocation) ----------------
__device__ float d_h0 [N_NODES * D];
__device__ float d_agg[N_NODES * D];
__device__ float d_g [N_GRAPHS * D];
__device__ float d_g2[N_GRAPHS * D];

__device__ uint d_hf_u[N_NODES * 32];           // fp16 X plane, 2 per uint
__device__ uint d_w1_u[3 * N_RELS * 2048];      // W^T fp16 plane

__device__ int d_counts[N_RELS];                // zero-init; self-resetting
__device__ int d_cursor[N_RELS];
__device__ int d_psrc[N_EDGES];
__device__ int d_pdst[N_EDGES];
__device__ int d_tile_rel [MAX_TILES];
__device__ int d_tile_base[MAX_TILES];
__device__ int d_tile_cnt [MAX_TILES];
__device__ int d_num_tiles;

// ---------------- helpers ----------------
__device__ __forceinline__ void red_add_v4(float* p, float a, float b, float c, float d) {
    asm volatile("red.global.add.v4.f32 [%0], {%1, %2, %3, %4};"
                 :: "l"(p), "f"(a), "f"(b), "f"(c), "f"(d) : "memory");
}

__device__ __forceinline__ void mma_f16(float acc[4], const uint a[4], uint b0, uint b1) {
    asm volatile("mma.sync.aligned.m16n8k16.row.col.f32.f16.f16.f32 "
                 "{%0,%1,%2,%3}, {%4,%5,%6,%7}, {%8,%9}, {%0,%1,%2,%3};"
                 : "+f"(acc[0]), "+f"(acc[1]), "+f"(acc[2]), "+f"(acc[3])
                 : "r"(a[0]), "r"(a[1]), "r"(a[2]), "r"(a[3]), "r"(b0), "r"(b1));
}

__device__ __forceinline__ void ldsm_x4(uint r[4], uint32_t addr) {
    asm volatile("ldmatrix.sync.aligned.m8n8.x4.shared.b16 {%0,%1,%2,%3}, [%4];"
                 : "=r"(r[0]), "=r"(r[1]), "=r"(r[2]), "=r"(r[3]) : "r"(addr));
}

__device__ __forceinline__ uint32_t smem_u32(const void* p) {
    uint32_t a;
    asm("{ .reg .u64 t; cvta.to.shared.u64 t, %1; cvt.u32.u64 %0, t; }" : "=r"(a) : "l"(p));
    return a;
}

__device__ __forceinline__ unsigned short h_bits(__half h) {
    return *reinterpret_cast<unsigned short*>(&h);
}
__device__ __forceinline__ uint pack_f16x2(float a, float b) {
    __half h0 = __float2half_rn(a);
    __half h1 = __float2half_rn(b);
    return (uint)h_bits(h0) | ((uint)h_bits(h1) << 16);
}

// ---------------- prep: conv_x + zero agg/g + conv_w + hist (fused) ---------
__global__ void prep_kernel(const float* __restrict__ nf,
                            const int* __restrict__ et,
                            const float* __restrict__ W1,
                            const float* __restrict__ W2,
                            const float* __restrict__ W3) {
    int idx = blockIdx.x * 256 + threadIdx.x;

    if (idx < N_NODES * 32) {
        float2 v = ((const float2*)nf)[idx];
        d_hf_u[idx] = pack_f16x2(v.x, v.y);
        ((float2*)d_agg)[idx] = make_float2(0.f, 0.f);
    }
    if (idx < N_GRAPHS * 32) ((float2*)d_g)[idx] = make_float2(0.f, 0.f);

    if (idx < 3 * N_RELS * 64) {
        int l = idx / (N_RELS * 64), rc = idx % (N_RELS * 64);
        int r = rc >> 6, c = rc & 63;
        const float* W = (l == 0 ? W1 : (l == 1 ? W2 : W3)) + (size_t)r * 4096 + c;
        uint4* o1 = (uint4*)(d_w1_u + ((size_t)l * N_RELS + r) * 2048);
#pragma unroll
        for (int q = 0; q < 8; q++) {
            uint u1[4];
#pragma unroll
            for (int p = 0; p < 4; p++) {
                float v0 = W[(q * 8 + p * 2 + 0) * 64];
                float v1 = W[(q * 8 + p * 2 + 1) * 64];
                u1[p] = pack_f16x2(v0, v1);
            }
            o1[c * 8 + q] = make_uint4(u1[0], u1[1], u1[2], u1[3]);
        }
    }

    if (blockIdx.x < 256) {
        __shared__ int sc[N_RELS];
        for (int i = threadIdx.x; i < N_RELS; i += 256) sc[i] = 0;
        __syncthreads();
        for (int e = blockIdx.x * 256 + threadIdx.x; e < N_EDGES; e += 256 * 256)
            atomicAdd(&sc[et[e]], 1);
        __syncthreads();
        for (int i = threadIdx.x; i < N_RELS; i += 256)
            if (sc[i]) atomicAdd(&d_counts[i], sc[i]);
    }
}

// ---------------- scan + tile table (self-resets d_counts) ----------------
__global__ void scan_tiles_kernel() {
    __shared__ int offs[N_RELS];
    __shared__ int tstart[N_RELS];
    __shared__ int tcnt[N_RELS];
    if (threadIdx.x == 0) {
        int off = 0, ts = 0;
        for (int r = 0; r < N_RELS; r++) {
            int c = d_counts[r];
            offs[r] = off; tstart[r] = ts; tcnt[r] = c;
            d_cursor[r] = off;
            off += c;
            ts += (c + TILE_M - 1) / TILE_M;
        }
        d_num_tiles = ts;
    }
    __syncthreads();
    for (int r = threadIdx.x; r < N_RELS; r += blockDim.x) {
        d_counts[r] = 0;
        int c = tcnt[r], base = offs[r], t0 = tstart[r];
        int nt = (c + TILE_M - 1) / TILE_M;
        for (int t = 0; t < nt; t++) {
            d_tile_rel [t0 + t] = r;
            d_tile_base[t0 + t] = base + t * TILE_M;
            int rem = c - t * TILE_M;
            d_tile_cnt [t0 + t] = rem < TILE_M ? rem : TILE_M;
        }
    }
}

#define SC_EPT 8
__global__ void scatter_kernel(const int* __restrict__ et,
                               const int* __restrict__ src,
                               const int* __restrict__ dst) {
    __shared__ int lcnt[N_RELS];
    __shared__ int lbase[N_RELS];
    int start = blockIdx.x * blockDim.x * SC_EPT;
    for (int i = threadIdx.x; i < N_RELS; i += blockDim.x) lcnt[i] = 0;
    __syncthreads();
    int myrel[SC_EPT];
#pragma unroll
    for (int q = 0; q < SC_EPT; q++) {
        int e = start + threadIdx.x + q * blockDim.x;
        int r = (e < N_EDGES) ? et[e] : -1;
        myrel[q] = r;
        if (r >= 0) atomicAdd(&lcnt[r], 1);
    }
    __syncthreads();
    for (int i = threadIdx.x; i < N_RELS; i += blockDim.x) {
        int c = lcnt[i];
        lbase[i] = c ? atomicAdd(&d_cursor[i], c) : 0;
        lcnt[i] = 0;
    }
    __syncthreads();
#pragma unroll
    for (int q = 0; q < SC_EPT; q++) {
        int e = start + threadIdx.x + q * blockDim.x;
        int r = myrel[q];
        if (r >= 0) {
            int pos = lbase[r] + atomicAdd(&lcnt[r], 1);
            d_psrc[pos] = src[e];
            d_pdst[pos] = dst[e];
        }
    }
}

// ---------------- RGCN layer: fp16 W, 2 barriers/tile, deferred scatter -----
// Warp grid: 4 edge-blocks(32 rows) x 4 col-quarters(16 cols).
// SMEM: X buf0 [0,16K) buf1 [16K,32K); W1 [32K,40K);
//       out [40K,72K); sd ring [72K, 72K+3*512)
// Per tile t: prefetch(t+1); W-load; wait 1; B1; MMA; staging; B3; scatter(t).
// Happens-before proof:
//  - prefetch(t+1) writes X[b^1]/sd[(t+1)%3]: all ldsm of X[b^1] (MMA t-1)
//    completed at B3(t-1); concurrent scatter(t-1) reads sd[(t-1)%3] (disjoint
//    slot, diff 2 mod 3) and sOut (not X).
//  - W-load(t): all MMA(t-1) done at B3(t-1); visibility to all warps via B1(t).
//  - staging(t) writes sOut: all scatter(t-1) sOut reads precede B1(t).
//  - scatter(t) reads sOut after B3(t) (staging visible).
__global__ void __launch_bounds__(512, 2) rgcn_mma_kernel(int layer)
{
    extern __shared__ __align__(16) uint smem[];
    int nt_total = d_num_tiles;
    int k = (nt_total + P_BLOCKS - 1) / P_BLOCKS;
    int t0 = (int)blockIdx.x * k;
    int t1 = t0 + k; if (t1 > nt_total) t1 = nt_total;
    if (t0 >= t1) return;

    int tid = threadIdx.x;
    uint sbase = smem_u32(smem);
    uint wb1 = sbase + 32768u;
    int* s_dstS = (int*)((char*)smem + 73728);   // [3][128]
    float* sOutF = (float*)((char*)smem + 40960);

    int lane = tid & 31, w = tid >> 5;
    int ebh = w & 3;          // edge block (32 rows)
    int cbq = w >> 2;         // col quarter (16 cols)
    int aSel = (lane >> 4) & 1;
    int aRowB = ebh * 32 + (lane & 15);
    int bRow = cbq * 16 + (lane & 7) + ((lane >> 4) & 1) * 8;
    int bSel = (lane >> 3) & 1;
    int g = lane >> 2, tq = lane & 3;

    // coalesced gather map: 8 threads per edge row (2 passes)
    int gm0 = tid >> 3, gc8 = tid & 7;
    // coalesced scatter map: 16 threads per edge row (4 passes)
    int sm0 = tid >> 4, sc16 = tid & 15;

    int cur_rel = -1;

    auto prefetch = [&](int t, int buf) {
        int base = d_tile_base[t];
        int cnt  = d_tile_cnt[t];
        uint xb = sbase + (uint)buf * 16384u;
        int* sd = s_dstS + (t % 3) * 128;
#pragma unroll
        for (int p = 0; p < 2; p++) {
            int m = gm0 + p * 64;
            int ei = base + m;
            int eic = ei < (N_EDGES - 1) ? ei : (N_EDGES - 1);
            int srow = d_psrc[eic];
            uint ssz = (m < cnt) ? 16u : 0u;
            const char* gsrc = (const char*)(d_hf_u + (size_t)srow * 32) + gc8 * 16;
            int ph = gc8 ^ (m & 7);
            uint dsts = xb + (uint)(m * 128 + ph * 16);
            asm volatile("cp.async.ca.shared.global [%0], [%1], 16, %2;"
                         :: "r"(dsts), "l"(gsrc), "r"(ssz) : "memory");
            if (gc8 == 0) sd[m] = (m < cnt) ? d_pdst[eic] : -1;
        }
        asm volatile("cp.async.commit_group;" ::: "memory");
    };

    prefetch(t0, 0);

    for (int t = t0; t < t1; t++) {
        int buf = (t - t0) & 1;
        bool has_next = (t + 1 < t1);
        if (has_next) prefetch(t + 1, buf ^ 1);   // full-iteration cover

        int rel = d_tile_rel[t];
        if (rel != cur_rel) {
            cur_rel = rel;
            const uint4* W1g = (const uint4*)(d_w1_u + ((size_t)layer * N_RELS + rel) * 2048);
            uint4* w14 = (uint4*)((char*)smem + 32768);
            int n = tid >> 3, c = tid & 7;
            int ph = c ^ (n & 7);
            w14[n * 8 + ph] = W1g[tid];
        }

        if (has_next) asm volatile("cp.async.wait_group 1;" ::: "memory");
        else          asm volatile("cp.async.wait_group 0;" ::: "memory");
        __syncthreads();                          // B1: X[t]/W/sd visible

        uint xbB = sbase + (uint)buf * 16384u;

        float acc[2][2][4];
#pragma unroll
        for (int a = 0; a < 2; a++)
#pragma unroll
            for (int b = 0; b < 2; b++) {
                acc[a][b][0] = acc[a][b][1] = acc[a][b][2] = acc[a][b][3] = 0.f;
            }

#pragma unroll
        for (int ks = 0; ks < 4; ks++) {
            int bChunk = (ks * 2 + bSel) ^ (bRow & 7);
            uint bAddr = wb1 + (uint)(bRow * 128 + bChunk * 16);
            uint bh[4];
            ldsm_x4(bh, bAddr);
#pragma unroll
            for (int mb = 0; mb < 2; mb++) {
                int aRow = aRowB + mb * 16;
                int aChunk = (ks * 2 + aSel) ^ (aRow & 7);
                uint aAddr = xbB + (uint)(aRow * 128 + aChunk * 16);
                uint ah[4];
                ldsm_x4(ah, aAddr);
                mma_f16(acc[mb][0], ah, bh[0], bh[1]);
                mma_f16(acc[mb][1], ah, bh[2], bh[3]);
            }
        }

        // stage into dedicated out region (XOR layout, 64-float rows)
#pragma unroll
        for (int mb = 0; mb < 2; mb++) {
#pragma unroll
            for (int n8 = 0; n8 < 2; n8++) {
                int R = ebh * 32 + mb * 16 + g;
                int C = cbq * 16 + n8 * 8 + 2 * tq;
                int pcA = C ^ ((R & 7) << 3);
                *(float2*)&sOutF[R * 64 + pcA] = make_float2(acc[mb][n8][0], acc[mb][n8][1]);
                int R2 = R + 8;
                int pcB = C ^ ((R2 & 7) << 3);
                *(float2*)&sOutF[R2 * 64 + pcB] = make_float2(acc[mb][n8][2], acc[mb][n8][3]);
            }
        }
        __syncthreads();                          // B3: staging visible; licenses
                                                  // next prefetch/W-load

        // coalesced scatter: 16 threads per edge -> whole 256B row per half-warp
        {
            int* sd = s_dstS + (t % 3) * 128;
#pragma unroll
            for (int p = 0; p < 4; p++) {
                int m = sm0 + p * 32;
                int dn = sd[m];
                if (dn >= 0) {
                    int pc = (sc16 * 4) ^ ((m & 7) << 3);
                    float4 v = *(const float4*)&sOutF[m * 64 + pc];
                    red_add_v4(d_agg + (size_t)dn * 64 + sc16 * 4, v.x, v.y, v.z, v.w);
                }
            }
        }
    }
}

// ---------------- bias + relu + fp16 convert + agg re-zero ----------------
__global__ void bias_relu_kernel(const float* __restrict__ b, int last) {
    int idx = blockIdx.x * blockDim.x + threadIdx.x;
    if (idx >= N_NODES * 32) return;
    int c0 = (idx * 2) & 63;
    float2 a = ((const float2*)d_agg)[idx];
    ((float2*)d_agg)[idx] = make_float2(0.f, 0.f);
    float v0 = fmaxf(a.x + b[c0],     0.0f);
    float v1 = fmaxf(a.y + b[c0 + 1], 0.0f);
    if (last) ((float2*)d_h0)[idx] = make_float2(v0, v1);
    d_hf_u[idx] = pack_f16x2(v0, v1);
}

// ---------------- graph sum-pool (reads d_h0) ----------------
__global__ void pool_kernel(const int* __restrict__ gid) {
    int idx = blockIdx.x * blockDim.x + threadIdx.x;
    if (idx >= N_NODES * 16) return;
    int n = idx >> 4, c4 = idx & 15;
    float4 v = ((const float4*)(d_h0 + (size_t)n * 64))[c4];
    float* p = d_g + (size_t)gid[n] * 64 + c4 * 4;
    red_add_v4(p, v.x, v.y, v.z, v.w);
}

// ---------------- FC layers ----------------
__global__ void fc64_kernel(int insel, int outsel,
                            const float* __restrict__ W,
                            const float* __restrict__ b) {
    int idx = blockIdx.x * blockDim.x + threadIdx.x;
    if (idx >= N_GRAPHS * 64) return;
    int r = idx >> 6, c = idx & 63;
    const float* x = (insel == 0 ? d_g : d_g2) + r * 64;
    float acc = b[c];
#pragma unroll
    for (int d = 0; d < 64; d++) acc = fmaf(x[d], W[d * 64 + c], acc);
    float v = fmaxf(acc, 0.0f);
    if (outsel == 0) d_g[idx] = v; else d_g2[idx] = v;
}

__global__ void pred_kernel(const float* __restrict__ W,
                            const float* __restrict__ b,
                            float* __restrict__ out) {
    int idx = blockIdx.x * blockDim.x + threadIdx.x;
    if (idx >= N_GRAPHS * 2) return;
    int r = idx >> 1, c = idx & 1;
    const float* x = d_g2 + r * 64;
    float acc = b[c];
#pragma unroll
    for (int d = 0; d < 64; d++) acc = fmaf(x[d], W[d * 2 + c], acc);
    out[idx] = acc;
}

// ---------------- launch ----------------
extern "C" void kernel_launch(void* const* d_in, const int* in_sizes, int n_in,
                              void* d_out, int out_size) {
    const float* node_feats = (const float*)d_in[0];
    const int*   etypes     = (const int*)d_in[1];
    const int*   src        = (const int*)d_in[2];
    const int*   dst        = (const int*)d_in[3];
    const int*   gid        = (const int*)d_in[4];
    const float* Wr[3] = { (const float*)d_in[5], (const float*)d_in[7], (const float*)d_in[9] };
    const float* br[3] = { (const float*)d_in[6], (const float*)d_in[8], (const float*)d_in[10] };
    const float* fcW[3] = { (const float*)d_in[11], (const float*)d_in[13], (const float*)d_in[15] };
    const float* fcb[3] = { (const float*)d_in[12], (const float*)d_in[14], (const float*)d_in[16] };
    const float* predW = (const float*)d_in[17];
    const float* predb = (const float*)d_in[18];

    static int smem_set = 0;
    if (!smem_set) {
        cudaFuncSetAttribute(rgcn_mma_kernel,
                             cudaFuncAttributeMaxDynamicSharedMemorySize, RGCN_SMEM);
        smem_set = 1;
    }

    const int pgrid = (N_NODES * 32 + 255) / 256;

    prep_kernel<<<pgrid, 256>>>(node_feats, etypes, Wr[0], Wr[1], Wr[2]);
    scan_tiles_kernel<<<1, 128>>>();
    scatter_kernel<<<(N_EDGES + 256 * SC_EPT - 1) / (256 * SC_EPT), 256>>>(etypes, src, dst);

    for (int L = 0; L < 3; L++) {
        rgcn_mma_kernel<<<P_BLOCKS, 512, RGCN_SMEM>>>(L);
        bias_relu_kernel<<<pgrid, 256>>>(br[L], L == 2 ? 1 : 0);
    }

    pool_kernel<<<(N_NODES * 16 + 255) / 256, 256>>>(gid);

    const int fgrid = (N_GRAPHS * 64 + 255) / 256;
    fc64_kernel<<<fgrid, 256>>>(0, 1, fcW[0], fcb[0]);
    fc64_kernel<<<fgrid, 256>>>(1, 0, fcW[1], fcb[1]);
    fc64_kernel<<<fgrid, 256>>>(0, 1, fcW[2], fcb[2]);
    pred_kernel<<<(N_GRAPHS * 2 + 255) / 256, 256>>>(predW, predb, (float*)d_out);
}

// round 14
// speedup vs baseline: 1.5150x; 1.0185x over previous
#include <cuda_runtime.h>
#include <cuda_fp16.h>
#include <cstdint>

typedef unsigned int uint;

#define N_NODES 50000
#define N_EDGES 800000
#define N_RELS  65
#define D       64
#define N_GRAPHS 512

#define TILE_M 64
#define MAX_TILES (N_EDGES / TILE_M + N_RELS)   // 12565
#define P_BLOCKS 592
#define RGCN_SMEM 41728  // X 2x8K | W 8K | out 16K | sd 3x256B

// ---------------- scratch (device globals; no allocation) ----------------
__device__ float d_h0 [N_NODES * D];
__device__ float d_agg[N_NODES * D];
__device__ float d_g [N_GRAPHS * D];
__device__ float d_g2[N_GRAPHS * D];

__device__ uint d_hf_u[N_NODES * 32];           // fp16 X plane, 2 per uint
__device__ uint d_w1_u[3 * N_RELS * 2048];      // W^T fp16 plane

__device__ int d_counts[N_RELS];                // zero-init; self-resetting
__device__ int d_cursor[N_RELS];
__device__ int d_psrc[N_EDGES];
__device__ int d_pdst[N_EDGES];
__device__ int d_tile_rel [MAX_TILES];
__device__ int d_tile_base[MAX_TILES];
__device__ int d_tile_cnt [MAX_TILES];
__device__ int d_num_tiles;

// ---------------- helpers ----------------
__device__ __forceinline__ void red_add_v4(float* p, float a, float b, float c, float d) {
    asm volatile("red.global.add.v4.f32 [%0], {%1, %2, %3, %4};"
                 :: "l"(p), "f"(a), "f"(b), "f"(c), "f"(d) : "memory");
}

__device__ __forceinline__ void mma_f16(float acc[4], const uint a[4], uint b0, uint b1) {
    asm volatile("mma.sync.aligned.m16n8k16.row.col.f32.f16.f16.f32 "
                 "{%0,%1,%2,%3}, {%4,%5,%6,%7}, {%8,%9}, {%0,%1,%2,%3};"
                 : "+f"(acc[0]), "+f"(acc[1]), "+f"(acc[2]), "+f"(acc[3])
                 : "r"(a[0]), "r"(a[1]), "r"(a[2]), "r"(a[3]), "r"(b0), "r"(b1));
}

__device__ __forceinline__ void ldsm_x4(uint r[4], uint32_t addr) {
    asm volatile("ldmatrix.sync.aligned.m8n8.x4.shared.b16 {%0,%1,%2,%3}, [%4];"
                 : "=r"(r[0]), "=r"(r[1]), "=r"(r[2]), "=r"(r[3]) : "r"(addr));
}

__device__ __forceinline__ uint32_t smem_u32(const void* p) {
    uint32_t a;
    asm("{ .reg .u64 t; cvta.to.shared.u64 t, %1; cvt.u32.u64 %0, t; }" : "=r"(a) : "l"(p));
    return a;
}

__device__ __forceinline__ unsigned short h_bits(__half h) {
    return *reinterpret_cast<unsigned short*>(&h);
}
__device__ __forceinline__ uint pack_f16x2(float a, float b) {
    __half h0 = __float2half_rn(a);
    __half h1 = __float2half_rn(b);
    return (uint)h_bits(h0) | ((uint)h_bits(h1) << 16);
}

// ---------------- prep: conv_x + zero agg/g + conv_w + hist (fused) ---------
__global__ void prep_kernel(const float* __restrict__ nf,
                            const int* __restrict__ et,
                            const float* __restrict__ W1,
                            const float* __restrict__ W2,
                            const float* __restrict__ W3) {
    int idx = blockIdx.x * 256 + threadIdx.x;

    if (idx < N_NODES * 32) {
        float2 v = ((const float2*)nf)[idx];
        d_hf_u[idx] = pack_f16x2(v.x, v.y);
        ((float2*)d_agg)[idx] = make_float2(0.f, 0.f);
    }
    if (idx < N_GRAPHS * 32) ((float2*)d_g)[idx] = make_float2(0.f, 0.f);

    if (idx < 3 * N_RELS * 64) {
        int l = idx / (N_RELS * 64), rc = idx % (N_RELS * 64);
        int r = rc >> 6, c = rc & 63;
        const float* W = (l == 0 ? W1 : (l == 1 ? W2 : W3)) + (size_t)r * 4096 + c;
        uint4* o1 = (uint4*)(d_w1_u + ((size_t)l * N_RELS + r) * 2048);
#pragma unroll
        for (int q = 0; q < 8; q++) {
            uint u1[4];
#pragma unroll
            for (int p = 0; p < 4; p++) {
                float v0 = W[(q * 8 + p * 2 + 0) * 64];
                float v1 = W[(q * 8 + p * 2 + 1) * 64];
                u1[p] = pack_f16x2(v0, v1);
            }
            o1[c * 8 + q] = make_uint4(u1[0], u1[1], u1[2], u1[3]);
        }
    }

    if (blockIdx.x < 256) {
        __shared__ int sc[N_RELS];
        for (int i = threadIdx.x; i < N_RELS; i += 256) sc[i] = 0;
        __syncthreads();
        for (int e = blockIdx.x * 256 + threadIdx.x; e < N_EDGES; e += 256 * 256)
            atomicAdd(&sc[et[e]], 1);
        __syncthreads();
        for (int i = threadIdx.x; i < N_RELS; i += 256)
            if (sc[i]) atomicAdd(&d_counts[i], sc[i]);
    }
}

// ---------------- scan + tile table (self-resets d_counts) ----------------
__global__ void scan_tiles_kernel() {
    __shared__ int offs[N_RELS];
    __shared__ int tstart[N_RELS];
    __shared__ int tcnt[N_RELS];
    if (threadIdx.x == 0) {
        int off = 0, ts = 0;
        for (int r = 0; r < N_RELS; r++) {
            int c = d_counts[r];
            offs[r] = off; tstart[r] = ts; tcnt[r] = c;
            d_cursor[r] = off;
            off += c;
            ts += (c + TILE_M - 1) / TILE_M;
        }
        d_num_tiles = ts;
    }
    __syncthreads();
    for (int r = threadIdx.x; r < N_RELS; r += blockDim.x) {
        d_counts[r] = 0;
        int c = tcnt[r], base = offs[r], t0 = tstart[r];
        int nt = (c + TILE_M - 1) / TILE_M;
        for (int t = 0; t < nt; t++) {
            d_tile_rel [t0 + t] = r;
            d_tile_base[t0 + t] = base + t * TILE_M;
            int rem = c - t * TILE_M;
            d_tile_cnt [t0 + t] = rem < TILE_M ? rem : TILE_M;
        }
    }
}

// ---------------- relation sort: coalesced writes via SMEM grouping ---------
#define SC_EPT 8
__global__ void scatter_kernel(const int* __restrict__ et,
                               const int* __restrict__ src,
                               const int* __restrict__ dst) {
    __shared__ int lcnt[N_RELS];
    __shared__ int lbase[N_RELS];
    __shared__ int lstart[N_RELS];
    __shared__ int2 sbuf[256 * SC_EPT];
    __shared__ int  gposb[256 * SC_EPT];
    int tid = threadIdx.x;
    int start = blockIdx.x * 256 * SC_EPT;
    for (int i = tid; i < N_RELS; i += 256) lcnt[i] = 0;
    __syncthreads();
    int myrel[SC_EPT];
#pragma unroll
    for (int q = 0; q < SC_EPT; q++) {
        int e = start + tid + q * 256;
        int r = (e < N_EDGES) ? et[e] : -1;
        myrel[q] = r;
        if (r >= 0) atomicAdd(&lcnt[r], 1);
    }
    __syncthreads();
    if (tid < N_RELS) {
        int c = lcnt[tid];
        lbase[tid] = c ? atomicAdd(&d_cursor[tid], c) : 0;
    }
    if (tid == 0) {
        int off = 0;
        for (int r = 0; r < N_RELS; r++) { lstart[r] = off; off += lcnt[r]; }
    }
    __syncthreads();
    if (tid < N_RELS) lcnt[tid] = 0;
    __syncthreads();
#pragma unroll
    for (int q = 0; q < SC_EPT; q++) {
        int e = start + tid + q * 256;
        int r = myrel[q];
        if (r >= 0) {
            int s = lstart[r] + atomicAdd(&lcnt[r], 1);
            sbuf[s] = make_int2(src[e], dst[e]);
            gposb[s] = lbase[r] + (s - lstart[r]);
        }
    }
    __syncthreads();
    int tot = N_EDGES - start;
    if (tot > 256 * SC_EPT) tot = 256 * SC_EPT;
    for (int i = tid; i < tot; i += 256) {
        int gp = gposb[i];
        int2 v = sbuf[i];
        d_psrc[gp] = v.x;
        d_pdst[gp] = v.y;
    }
}

// ---------------- RGCN layer: 256 threads, 4 blocks/SM, R13 schedule --------
// Warp grid: 2 edge-blocks(32 rows) x 4 col-quarters(16 cols).
// SMEM: X buf0 [0,8K) buf1 [8K,16K); W1 [16K,24K);
//       out [24K,40K); sd ring [40K, 40K+3*256)
__global__ void __launch_bounds__(256, 4) rgcn_mma_kernel(int layer)
{
    extern __shared__ __align__(16) uint smem[];
    int nt_total = d_num_tiles;
    int k = (nt_total + P_BLOCKS - 1) / P_BLOCKS;
    int t0 = (int)blockIdx.x * k;
    int t1 = t0 + k; if (t1 > nt_total) t1 = nt_total;
    if (t0 >= t1) return;

    int tid = threadIdx.x;
    uint sbase = smem_u32(smem);
    uint wb1 = sbase + 16384u;
    float* sOutF = (float*)((char*)smem + 24576);
    int* s_dstS = (int*)((char*)smem + 40960);   // [3][64]

    int lane = tid & 31, w = tid >> 5;
    int ebh = w & 1;          // edge block (32 rows)
    int cbq = w >> 1;         // col quarter (16 cols)
    int aSel = (lane >> 4) & 1;
    int aRowB = ebh * 32 + (lane & 15);
    int bRow = cbq * 16 + (lane & 7) + ((lane >> 4) & 1) * 8;
    int bSel = (lane >> 3) & 1;
    int g = lane >> 2, tq = lane & 3;

    // coalesced gather map: 8 threads per edge row (2 passes of 32 edges)
    int gm0 = tid >> 3, gc8 = tid & 7;
    // coalesced scatter map: 16 threads per edge row (4 passes of 16 edges)
    int sm0 = tid >> 4, sc16 = tid & 15;

    int cur_rel = -1;

    auto prefetch = [&](int t, int buf) {
        int base = d_tile_base[t];
        int cnt  = d_tile_cnt[t];
        uint xb = sbase + (uint)buf * 8192u;
        int* sd = s_dstS + (t % 3) * 64;
#pragma unroll
        for (int p = 0; p < 2; p++) {
            int m = gm0 + p * 32;
            int ei = base + m;
            int eic = ei < (N_EDGES - 1) ? ei : (N_EDGES - 1);
            int srow = d_psrc[eic];
            uint ssz = (m < cnt) ? 16u : 0u;
            const char* gsrc = (const char*)(d_hf_u + (size_t)srow * 32) + gc8 * 16;
            int ph = gc8 ^ (m & 7);
            uint dsts = xb + (uint)(m * 128 + ph * 16);
            asm volatile("cp.async.ca.shared.global [%0], [%1], 16, %2;"
                         :: "r"(dsts), "l"(gsrc), "r"(ssz) : "memory");
            if (gc8 == 0) sd[m] = (m < cnt) ? d_pdst[eic] : -1;
        }
        asm volatile("cp.async.commit_group;" ::: "memory");
    };

    prefetch(t0, 0);

    for (int t = t0; t < t1; t++) {
        int buf = (t - t0) & 1;
        bool has_next = (t + 1 < t1);
        if (has_next) prefetch(t + 1, buf ^ 1);   // full-iteration cover

        int rel = d_tile_rel[t];
        if (rel != cur_rel) {
            cur_rel = rel;
            const uint4* W1g = (const uint4*)(d_w1_u + ((size_t)layer * N_RELS + rel) * 2048);
            uint4* w14 = (uint4*)((char*)smem + 16384);
#pragma unroll
            for (int i = 0; i < 2; i++) {
                int idx = tid + i * 256;
                int n = idx >> 3, c = idx & 7;
                int ph = c ^ (n & 7);
                w14[n * 8 + ph] = W1g[idx];
            }
        }

        if (has_next) asm volatile("cp.async.wait_group 1;" ::: "memory");
        else          asm volatile("cp.async.wait_group 0;" ::: "memory");
        __syncthreads();                          // B1: X[t]/W/sd visible

        uint xbB = sbase + (uint)buf * 8192u;

        float acc[2][2][4];
#pragma unroll
        for (int a = 0; a < 2; a++)
#pragma unroll
            for (int b = 0; b < 2; b++) {
                acc[a][b][0] = acc[a][b][1] = acc[a][b][2] = acc[a][b][3] = 0.f;
            }

#pragma unroll
        for (int ks = 0; ks < 4; ks++) {
            int bChunk = (ks * 2 + bSel) ^ (bRow & 7);
            uint bAddr = wb1 + (uint)(bRow * 128 + bChunk * 16);
            uint bh[4];
            ldsm_x4(bh, bAddr);
#pragma unroll
            for (int mb = 0; mb < 2; mb++) {
                int aRow = aRowB + mb * 16;
                int aChunk = (ks * 2 + aSel) ^ (aRow & 7);
                uint aAddr = xbB + (uint)(aRow * 128 + aChunk * 16);
                uint ah[4];
                ldsm_x4(ah, aAddr);
                mma_f16(acc[mb][0], ah, bh[0], bh[1]);
                mma_f16(acc[mb][1], ah, bh[2], bh[3]);
            }
        }

        // stage into out region (XOR layout, 64-float rows)
#pragma unroll
        for (int mb = 0; mb < 2; mb++) {
#pragma unroll
            for (int n8 = 0; n8 < 2; n8++) {
                int R = ebh * 32 + mb * 16 + g;
                int C = cbq * 16 + n8 * 8 + 2 * tq;
                int pcA = C ^ ((R & 7) << 3);
                *(float2*)&sOutF[R * 64 + pcA] = make_float2(acc[mb][n8][0], acc[mb][n8][1]);
                int R2 = R + 8;
                int pcB = C ^ ((R2 & 7) << 3);
                *(float2*)&sOutF[R2 * 64 + pcB] = make_float2(acc[mb][n8][2], acc[mb][n8][3]);
            }
        }
        __syncthreads();                          // B3: staging visible; licenses
                                                  // next prefetch/W-load

        // coalesced scatter: 16 threads per edge -> whole 256B row per half-warp
        {
            int* sd = s_dstS + (t % 3) * 64;
#pragma unroll
            for (int p = 0; p < 4; p++) {
                int m = sm0 + p * 16;
                int dn = sd[m];
                if (dn >= 0) {
                    int pc = (sc16 * 4) ^ ((m & 7) << 3);
                    float4 v = *(const float4*)&sOutF[m * 64 + pc];
                    red_add_v4(d_agg + (size_t)dn * 64 + sc16 * 4, v.x, v.y, v.z, v.w);
                }
            }
        }
    }
}

// ---------------- bias + relu + fp16 convert + agg re-zero ----------------
__global__ void bias_relu_kernel(const float* __restrict__ b, int last) {
    int idx = blockIdx.x * blockDim.x + threadIdx.x;
    if (idx >= N_NODES * 32) return;
    int c0 = (idx * 2) & 63;
    float2 a = ((const float2*)d_agg)[idx];
    ((float2*)d_agg)[idx] = make_float2(0.f, 0.f);
    float v0 = fmaxf(a.x + b[c0],     0.0f);
    float v1 = fmaxf(a.y + b[c0 + 1], 0.0f);
    if (last) ((float2*)d_h0)[idx] = make_float2(v0, v1);
    d_hf_u[idx] = pack_f16x2(v0, v1);
}

// ---------------- graph sum-pool (reads d_h0) ----------------
__global__ void pool_kernel(const int* __restrict__ gid) {
    int idx = blockIdx.x * blockDim.x + threadIdx.x;
    if (idx >= N_NODES * 16) return;
    int n = idx >> 4, c4 = idx & 15;
    float4 v = ((const float4*)(d_h0 + (size_t)n * 64))[c4];
    float* p = d_g + (size_t)gid[n] * 64 + c4 * 4;
    red_add_v4(p, v.x, v.y, v.z, v.w);
}

// ---------------- FC layers ----------------
__global__ void fc64_kernel(int insel, int outsel,
                            const float* __restrict__ W,
                            const float* __restrict__ b) {
    int idx = blockIdx.x * blockDim.x + threadIdx.x;
    if (idx >= N_GRAPHS * 64) return;
    int r = idx >> 6, c = idx & 63;
    const float* x = (insel == 0 ? d_g : d_g2) + r * 64;
    float acc = b[c];
#pragma unroll
    for (int d = 0; d < 64; d++) acc = fmaf(x[d], W[d * 64 + c], acc);
    float v = fmaxf(acc, 0.0f);
    if (outsel == 0) d_g[idx] = v; else d_g2[idx] = v;
}

__global__ void pred_kernel(const float* __restrict__ W,
                            const float* __restrict__ b,
                            float* __restrict__ out) {
    int idx = blockIdx.x * blockDim.x + threadIdx.x;
    if (idx >= N_GRAPHS * 2) return;
    int r = idx >> 1, c = idx & 1;
    const float* x = d_g2 + r * 64;
    float acc = b[c];
#pragma unroll
    for (int d = 0; d < 64; d++) acc = fmaf(x[d], W[d * 2 + c], acc);
    out[idx] = acc;
}

// ---------------- launch ----------------
extern "C" void kernel_launch(void* const* d_in, const int* in_sizes, int n_in,
                              void* d_out, int out_size) {
    const float* node_feats = (const float*)d_in[0];
    const int*   etypes     = (const int*)d_in[1];
    const int*   src        = (const int*)d_in[2];
    const int*   dst        = (const int*)d_in[3];
    const int*   gid        = (const int*)d_in[4];
    const float* Wr[3] = { (const float*)d_in[5], (const float*)d_in[7], (const float*)d_in[9] };
    const float* br[3] = { (const float*)d_in[6], (const float*)d_in[8], (const float*)d_in[10] };
    const float* fcW[3] = { (const float*)d_in[11], (const float*)d_in[13], (const float*)d_in[15] };
    const float* fcb[3] = { (const float*)d_in[12], (const float*)d_in[14], (const float*)d_in[16] };
    const float* predW = (const float*)d_in[17];
    const float* predb = (const float*)d_in[18];

    static int smem_set = 0;
    if (!smem_set) {
        cudaFuncSetAttribute(rgcn_mma_kernel,
                             cudaFuncAttributeMaxDynamicSharedMemorySize, RGCN_SMEM);
        smem_set = 1;
    }

    const int pgrid = (N_NODES * 32 + 255) / 256;

    prep_kernel<<<pgrid, 256>>>(node_feats, etypes, Wr[0], Wr[1], Wr[2]);
    scan_tiles_kernel<<<1, 128>>>();
    scatter_kernel<<<(N_EDGES + 256 * SC_EPT - 1) / (256 * SC_EPT), 256>>>(etypes, src, dst);

    for (int L = 0; L < 3; L++) {
        rgcn_mma_kernel<<<P_BLOCKS, 256, RGCN_SMEM>>>(L);
        bias_relu_kernel<<<pgrid, 256>>>(br[L], L == 2 ? 1 : 0);
    }

    pool_kernel<<<(N_NODES * 16 + 255) / 256, 256>>>(gid);

    const int fgrid = (N_GRAPHS * 64 + 255) / 256;
    fc64_kernel<<<fgrid, 256>>>(0, 1, fcW[0], fcb[0]);
    fc64_kernel<<<fgrid, 256>>>(1, 0, fcW[1], fcb[1]);
    fc64_kernel<<<fgrid, 256>>>(0, 1, fcW[2], fcb[2]);
    pred_kernel<<<(N_GRAPHS * 2 + 255) / 256, 256>>>(predW, predb, (float*)d_out);
}

// round 15
// speedup vs baseline: 1.7131x; 1.1307x over previous
#include <cuda_runtime.h>
#include <cuda_fp16.h>
#include <cstdint>

typedef unsigned int uint;

#define N_NODES 50000
#define N_EDGES 800000
#define N_RELS  65
#define D       64
#define N_GRAPHS 512

#define TILE_M 64
#define MAX_TILES (N_EDGES / TILE_M + N_RELS)   // 12565
#define P_BLOCKS 592
#define RGCN_SMEM 41728  // X 2x8K | W 8K | out 16K | sd 3x256B

// ---------------- scratch (device globals; no allocation) ----------------
__device__ float d_agg[N_NODES * D];
__device__ float d_g [N_GRAPHS * D];

__device__ uint d_hf_u[N_NODES * 32];           // fp16 X plane, 2 per uint
__device__ uint d_w1_u[3 * N_RELS * 2048];      // W^T fp16 plane

__device__ int d_counts[N_RELS];                // zero-init; self-resetting
__device__ int d_cursor[N_RELS];
__device__ int d_psrc[N_EDGES];
__device__ int d_pdst[N_EDGES];
__device__ int d_tile_rel [MAX_TILES];
__device__ int d_tile_base[MAX_TILES];
__device__ int d_tile_cnt [MAX_TILES];
__device__ int d_num_tiles;

// ---------------- helpers ----------------
__device__ __forceinline__ void red_add_v4(float* p, float a, float b, float c, float d) {
    asm volatile("red.global.add.v4.f32 [%0], {%1, %2, %3, %4};"
                 :: "l"(p), "f"(a), "f"(b), "f"(c), "f"(d) : "memory");
}

__device__ __forceinline__ void mma_f16(float acc[4], const uint a[4], uint b0, uint b1) {
    asm volatile("mma.sync.aligned.m16n8k16.row.col.f32.f16.f16.f32 "
                 "{%0,%1,%2,%3}, {%4,%5,%6,%7}, {%8,%9}, {%0,%1,%2,%3};"
                 : "+f"(acc[0]), "+f"(acc[1]), "+f"(acc[2]), "+f"(acc[3])
                 : "r"(a[0]), "r"(a[1]), "r"(a[2]), "r"(a[3]), "r"(b0), "r"(b1));
}

__device__ __forceinline__ void ldsm_x4(uint r[4], uint32_t addr) {
    asm volatile("ldmatrix.sync.aligned.m8n8.x4.shared.b16 {%0,%1,%2,%3}, [%4];"
                 : "=r"(r[0]), "=r"(r[1]), "=r"(r[2]), "=r"(r[3]) : "r"(addr));
}

__device__ __forceinline__ uint32_t smem_u32(const void* p) {
    uint32_t a;
    asm("{ .reg .u64 t; cvta.to.shared.u64 t, %1; cvt.u32.u64 %0, t; }" : "=r"(a) : "l"(p));
    return a;
}

__device__ __forceinline__ unsigned short h_bits(__half h) {
    return *reinterpret_cast<unsigned short*>(&h);
}
__device__ __forceinline__ uint pack_f16x2(float a, float b) {
    __half h0 = __float2half_rn(a);
    __half h1 = __float2half_rn(b);
    return (uint)h_bits(h0) | ((uint)h_bits(h1) << 16);
}

// ---------------- prep: conv_x + zero agg/g + conv_w + hist (fused) ---------
__global__ void prep_kernel(const float* __restrict__ nf,
                            const int* __restrict__ et,
                            const float* __restrict__ W1,
                            const float* __restrict__ W2,
                            const float* __restrict__ W3) {
    int idx = blockIdx.x * 256 + threadIdx.x;

    if (idx < N_NODES * 32) {
        float2 v = ((const float2*)nf)[idx];
        d_hf_u[idx] = pack_f16x2(v.x, v.y);
        ((float2*)d_agg)[idx] = make_float2(0.f, 0.f);
    }
    if (idx < N_GRAPHS * 32) ((float2*)d_g)[idx] = make_float2(0.f, 0.f);

    if (idx < 3 * N_RELS * 64) {
        int l = idx / (N_RELS * 64), rc = idx % (N_RELS * 64);
        int r = rc >> 6, c = rc & 63;
        const float* W = (l == 0 ? W1 : (l == 1 ? W2 : W3)) + (size_t)r * 4096 + c;
        uint4* o1 = (uint4*)(d_w1_u + ((size_t)l * N_RELS + r) * 2048);
#pragma unroll
        for (int q = 0; q < 8; q++) {
            uint u1[4];
#pragma unroll
            for (int p = 0; p < 4; p++) {
                float v0 = W[(q * 8 + p * 2 + 0) * 64];
                float v1 = W[(q * 8 + p * 2 + 1) * 64];
                u1[p] = pack_f16x2(v0, v1);
            }
            o1[c * 8 + q] = make_uint4(u1[0], u1[1], u1[2], u1[3]);
        }
    }

    if (blockIdx.x < 256) {
        __shared__ int sc[N_RELS];
        for (int i = threadIdx.x; i < N_RELS; i += 256) sc[i] = 0;
        __syncthreads();
        for (int e = blockIdx.x * 256 + threadIdx.x; e < N_EDGES; e += 256 * 256)
            atomicAdd(&sc[et[e]], 1);
        __syncthreads();
        for (int i = threadIdx.x; i < N_RELS; i += 256)
            if (sc[i]) atomicAdd(&d_counts[i], sc[i]);
    }
}

// ---------------- scan + tile table (self-resets d_counts) ----------------
__global__ void scan_tiles_kernel() {
    __shared__ int offs[N_RELS];
    __shared__ int tstart[N_RELS];
    __shared__ int tcnt[N_RELS];
    if (threadIdx.x == 0) {
        int off = 0, ts = 0;
        for (int r = 0; r < N_RELS; r++) {
            int c = d_counts[r];
            offs[r] = off; tstart[r] = ts; tcnt[r] = c;
            d_cursor[r] = off;
            off += c;
            ts += (c + TILE_M - 1) / TILE_M;
        }
        d_num_tiles = ts;
    }
    __syncthreads();
    for (int r = threadIdx.x; r < N_RELS; r += blockDim.x) {
        d_counts[r] = 0;
        int c = tcnt[r], base = offs[r], t0 = tstart[r];
        int nt = (c + TILE_M - 1) / TILE_M;
        for (int t = 0; t < nt; t++) {
            d_tile_rel [t0 + t] = r;
            d_tile_base[t0 + t] = base + t * TILE_M;
            int rem = c - t * TILE_M;
            d_tile_cnt [t0 + t] = rem < TILE_M ? rem : TILE_M;
        }
    }
}

// ---------------- relation sort: coalesced writes via SMEM grouping ---------
#define SC_EPT 8
__global__ void scatter_kernel(const int* __restrict__ et,
                               const int* __restrict__ src,
                               const int* __restrict__ dst) {
    __shared__ int lcnt[N_RELS];
    __shared__ int lbase[N_RELS];
    __shared__ int lstart[N_RELS];
    __shared__ int2 sbuf[256 * SC_EPT];
    __shared__ int  gposb[256 * SC_EPT];
    int tid = threadIdx.x;
    int start = blockIdx.x * 256 * SC_EPT;
    for (int i = tid; i < N_RELS; i += 256) lcnt[i] = 0;
    __syncthreads();
    int myrel[SC_EPT];
#pragma unroll
    for (int q = 0; q < SC_EPT; q++) {
        int e = start + tid + q * 256;
        int r = (e < N_EDGES) ? et[e] : -1;
        myrel[q] = r;
        if (r >= 0) atomicAdd(&lcnt[r], 1);
    }
    __syncthreads();
    if (tid < N_RELS) {
        int c = lcnt[tid];
        lbase[tid] = c ? atomicAdd(&d_cursor[tid], c) : 0;
    }
    if (tid == 0) {
        int off = 0;
        for (int r = 0; r < N_RELS; r++) { lstart[r] = off; off += lcnt[r]; }
    }
    __syncthreads();
    if (tid < N_RELS) lcnt[tid] = 0;
    __syncthreads();
#pragma unroll
    for (int q = 0; q < SC_EPT; q++) {
        int e = start + tid + q * 256;
        int r = myrel[q];
        if (r >= 0) {
            int s = lstart[r] + atomicAdd(&lcnt[r], 1);
            sbuf[s] = make_int2(src[e], dst[e]);
            gposb[s] = lbase[r] + (s - lstart[r]);
        }
    }
    __syncthreads();
    int tot = N_EDGES - start;
    if (tot > 256 * SC_EPT) tot = 256 * SC_EPT;
    for (int i = tid; i < tot; i += 256) {
        int gp = gposb[i];
        int2 v = sbuf[i];
        d_psrc[gp] = v.x;
        d_pdst[gp] = v.y;
    }
}

// ---------------- RGCN layer: 256 threads, 4 blocks/SM, R13 schedule --------
// Warp grid: 2 edge-blocks(32 rows) x 4 col-quarters(16 cols).
// SMEM: X buf0 [0,8K) buf1 [8K,16K); W1 [16K,24K);
//       out [24K,40K); sd ring [40K, 40K+3*256)
__global__ void __launch_bounds__(256, 4) rgcn_mma_kernel(int layer)
{
    extern __shared__ __align__(16) uint smem[];
    int nt_total = d_num_tiles;
    int k = (nt_total + P_BLOCKS - 1) / P_BLOCKS;
    int t0 = (int)blockIdx.x * k;
    int t1 = t0 + k; if (t1 > nt_total) t1 = nt_total;
    if (t0 >= t1) return;

    int tid = threadIdx.x;
    uint sbase = smem_u32(smem);
    uint wb1 = sbase + 16384u;
    float* sOutF = (float*)((char*)smem + 24576);
    int* s_dstS = (int*)((char*)smem + 40960);   // [3][64]

    int lane = tid & 31, w = tid >> 5;
    int ebh = w & 1;          // edge block (32 rows)
    int cbq = w >> 1;         // col quarter (16 cols)
    int aSel = (lane >> 4) & 1;
    int aRowB = ebh * 32 + (lane & 15);
    int bRow = cbq * 16 + (lane & 7) + ((lane >> 4) & 1) * 8;
    int bSel = (lane >> 3) & 1;
    int g = lane >> 2, tq = lane & 3;

    // coalesced gather map: 8 threads per edge row (2 passes of 32 edges)
    int gm0 = tid >> 3, gc8 = tid & 7;
    // coalesced scatter map: 16 threads per edge row (4 passes of 16 edges)
    int sm0 = tid >> 4, sc16 = tid & 15;

    int cur_rel = -1;

    auto prefetch = [&](int t, int buf) {
        int base = d_tile_base[t];
        int cnt  = d_tile_cnt[t];
        uint xb = sbase + (uint)buf * 8192u;
        int* sd = s_dstS + (t % 3) * 64;
#pragma unroll
        for (int p = 0; p < 2; p++) {
            int m = gm0 + p * 32;
            int ei = base + m;
            int eic = ei < (N_EDGES - 1) ? ei : (N_EDGES - 1);
            int srow = d_psrc[eic];
            uint ssz = (m < cnt) ? 16u : 0u;
            const char* gsrc = (const char*)(d_hf_u + (size_t)srow * 32) + gc8 * 16;
            int ph = gc8 ^ (m & 7);
            uint dsts = xb + (uint)(m * 128 + ph * 16);
            asm volatile("cp.async.cg.shared.global [%0], [%1], 16, %2;"
                         :: "r"(dsts), "l"(gsrc), "r"(ssz) : "memory");
            if (gc8 == 0) sd[m] = (m < cnt) ? d_pdst[eic] : -1;
        }
        asm volatile("cp.async.commit_group;" ::: "memory");
    };

    prefetch(t0, 0);

    for (int t = t0; t < t1; t++) {
        int buf = (t - t0) & 1;
        bool has_next = (t + 1 < t1);
        if (has_next) prefetch(t + 1, buf ^ 1);   // full-iteration cover

        int rel = d_tile_rel[t];
        if (rel != cur_rel) {
            cur_rel = rel;
            const uint4* W1g = (const uint4*)(d_w1_u + ((size_t)layer * N_RELS + rel) * 2048);
            uint4* w14 = (uint4*)((char*)smem + 16384);
#pragma unroll
            for (int i = 0; i < 2; i++) {
                int idx = tid + i * 256;
                int n = idx >> 3, c = idx & 7;
                int ph = c ^ (n & 7);
                w14[n * 8 + ph] = W1g[idx];
            }
        }

        if (has_next) asm volatile("cp.async.wait_group 1;" ::: "memory");
        else          asm volatile("cp.async.wait_group 0;" ::: "memory");
        __syncthreads();                          // B1: X[t]/W/sd visible

        uint xbB = sbase + (uint)buf * 8192u;

        float acc[2][2][4];
#pragma unroll
        for (int a = 0; a < 2; a++)
#pragma unroll
            for (int b = 0; b < 2; b++) {
                acc[a][b][0] = acc[a][b][1] = acc[a][b][2] = acc[a][b][3] = 0.f;
            }

#pragma unroll
        for (int ks = 0; ks < 4; ks++) {
            int bChunk = (ks * 2 + bSel) ^ (bRow & 7);
            uint bAddr = wb1 + (uint)(bRow * 128 + bChunk * 16);
            uint bh[4];
            ldsm_x4(bh, bAddr);
#pragma unroll
            for (int mb = 0; mb < 2; mb++) {
                int aRow = aRowB + mb * 16;
                int aChunk = (ks * 2 + aSel) ^ (aRow & 7);
                uint aAddr = xbB + (uint)(aRow * 128 + aChunk * 16);
                uint ah[4];
                ldsm_x4(ah, aAddr);
                mma_f16(acc[mb][0], ah, bh[0], bh[1]);
                mma_f16(acc[mb][1], ah, bh[2], bh[3]);
            }
        }

        // stage into out region (XOR layout, 64-float rows)
#pragma unroll
        for (int mb = 0; mb < 2; mb++) {
#pragma unroll
            for (int n8 = 0; n8 < 2; n8++) {
                int R = ebh * 32 + mb * 16 + g;
                int C = cbq * 16 + n8 * 8 + 2 * tq;
                int pcA = C ^ ((R & 7) << 3);
                *(float2*)&sOutF[R * 64 + pcA] = make_float2(acc[mb][n8][0], acc[mb][n8][1]);
                int R2 = R + 8;
                int pcB = C ^ ((R2 & 7) << 3);
                *(float2*)&sOutF[R2 * 64 + pcB] = make_float2(acc[mb][n8][2], acc[mb][n8][3]);
            }
        }
        __syncthreads();                          // B3: staging visible; licenses
                                                  // next prefetch/W-load

        // coalesced scatter: 16 threads per edge -> whole 256B row per half-warp
        {
            int* sd = s_dstS + (t % 3) * 64;
#pragma unroll
            for (int p = 0; p < 4; p++) {
                int m = sm0 + p * 16;
                int dn = sd[m];
                if (dn >= 0) {
                    int pc = (sc16 * 4) ^ ((m & 7) << 3);
                    float4 v = *(const float4*)&sOutF[m * 64 + pc];
                    red_add_v4(d_agg + (size_t)dn * 64 + sc16 * 4, v.x, v.y, v.z, v.w);
                }
            }
        }
    }
}

// ---------------- bias + relu (+fp16 convert | +fused pool) + agg re-zero ---
// 4 channels per thread (float4). last==0: write hf pairs. last==1: red_add to g.
__global__ void bias_relu_kernel(const float* __restrict__ b,
                                 const int* __restrict__ gid, int last) {
    int idx = blockIdx.x * blockDim.x + threadIdx.x;
    if (idx >= N_NODES * 16) return;
    int n = idx >> 4;
    int c0 = (idx & 15) * 4;
    float4 a = ((const float4*)d_agg)[idx];
    ((float4*)d_agg)[idx] = make_float4(0.f, 0.f, 0.f, 0.f);
    float v0 = fmaxf(a.x + b[c0],     0.0f);
    float v1 = fmaxf(a.y + b[c0 + 1], 0.0f);
    float v2 = fmaxf(a.z + b[c0 + 2], 0.0f);
    float v3 = fmaxf(a.w + b[c0 + 3], 0.0f);
    if (last) {
        float* p = d_g + (size_t)gid[n] * 64 + c0;
        red_add_v4(p, v0, v1, v2, v3);
    } else {
        uint2 hv = make_uint2(pack_f16x2(v0, v1), pack_f16x2(v2, v3));
        ((uint2*)d_hf_u)[idx] = hv;
    }
}

// ---------------- fused FC chain: g -> fc1 -> fc2 -> fc3 -> pred -> out -----
// Block = 256 threads = 4 graph rows x 64 cols; chain through SMEM.
__global__ void fc_fused_kernel(const float* __restrict__ W1, const float* __restrict__ b1,
                                const float* __restrict__ W2, const float* __restrict__ b2,
                                const float* __restrict__ W3, const float* __restrict__ b3,
                                const float* __restrict__ pW, const float* __restrict__ pb,
                                float* __restrict__ out) {
    __shared__ float xs[2][4][64];
    int r4 = threadIdx.x >> 6, c = threadIdx.x & 63;
    int row = blockIdx.x * 4 + r4;

    xs[0][r4][c] = d_g[row * 64 + c];
    __syncthreads();

    const float* Ws[3] = { W1, W2, W3 };
    const float* bs[3] = { b1, b2, b3 };
#pragma unroll
    for (int l = 0; l < 3; l++) {
        int s = l & 1;
        float acc = bs[l][c];
        const float* x = xs[s][r4];
        const float* W = Ws[l];
#pragma unroll
        for (int d = 0; d < 64; d++) acc = fmaf(x[d], W[d * 64 + c], acc);
        __syncthreads();
        xs[s ^ 1][r4][c] = fmaxf(acc, 0.0f);
        __syncthreads();
    }

    if (c < 2) {
        float acc = pb[c];
        const float* x = xs[1][r4];
#pragma unroll
        for (int d = 0; d < 64; d++) acc = fmaf(x[d], pW[d * 2 + c], acc);
        out[row * 2 + c] = acc;
    }
}

// ---------------- launch ----------------
extern "C" void kernel_launch(void* const* d_in, const int* in_sizes, int n_in,
                              void* d_out, int out_size) {
    const float* node_feats = (const float*)d_in[0];
    const int*   etypes     = (const int*)d_in[1];
    const int*   src        = (const int*)d_in[2];
    const int*   dst        = (const int*)d_in[3];
    const int*   gid        = (const int*)d_in[4];
    const float* Wr[3] = { (const float*)d_in[5], (const float*)d_in[7], (const float*)d_in[9] };
    const float* br[3] = { (const float*)d_in[6], (const float*)d_in[8], (const float*)d_in[10] };
    const float* fcW[3] = { (const float*)d_in[11], (const float*)d_in[13], (const float*)d_in[15] };
    const float* fcb[3] = { (const float*)d_in[12], (const float*)d_in[14], (const float*)d_in[16] };
    const float* predW = (const float*)d_in[17];
    const float* predb = (const float*)d_in[18];

    static int smem_set = 0;
    if (!smem_set) {
        cudaFuncSetAttribute(rgcn_mma_kernel,
                             cudaFuncAttributeMaxDynamicSharedMemorySize, RGCN_SMEM);
        smem_set = 1;
    }

    const int pgrid = (N_NODES * 32 + 255) / 256;
    const int bgrid = (N_NODES * 16 + 255) / 256;

    prep_kernel<<<pgrid, 256>>>(node_feats, etypes, Wr[0], Wr[1], Wr[2]);
    scan_tiles_kernel<<<1, 128>>>();
    scatter_kernel<<<(N_EDGES + 256 * SC_EPT - 1) / (256 * SC_EPT), 256>>>(etypes, src, dst);

    for (int L = 0; L < 3; L++) {
        rgcn_mma_kernel<<<P_BLOCKS, 256, RGCN_SMEM>>>(L);
        bias_relu_kernel<<<bgrid, 256>>>(br[L], gid, L == 2 ? 1 : 0);
    }

    fc_fused_kernel<<<N_GRAPHS / 4, 256>>>(fcW[0], fcb[0], fcW[1], fcb[1],
                                           fcW[2], fcb[2], predW, predb,
                                           (float*)d_out);
}